// round 2
// baseline (speedup 1.0000x reference)
#include <cuda_runtime.h>

typedef unsigned long long ull;

// Problem constants
#define NB   16
#define NT   8
#define NK   64
#define CIN  128
#define COUT 128
#define HH   64
#define WW   64
// per-b weight slice = COUT*CIN*25 = 409600 floats

// Scratch: layer params transposed to [b][c][ij][oc]  (b stride 409600, c stride 3200, ij stride 128)
__device__ float g_lp[NB * 409600];
// coeff packed over b-pairs: [k][pair p] -> f32x2 {coeff[2p][k], coeff[2p+1][k]}
__device__ ull g_coeff2[NK * 8];

__device__ __forceinline__ ull bcast2(float x) {
    ull r; asm("mov.b64 %0, {%1, %1};" : "=l"(r) : "f"(x)); return r;
}
__device__ __forceinline__ ull pack2(float lo, float hi) {
    ull r; asm("mov.b64 %0, {%1, %2};" : "=l"(r) : "f"(lo), "f"(hi)); return r;
}
__device__ __forceinline__ void unpack2(ull v, float& lo, float& hi) {
    asm("mov.b64 {%0, %1}, %2;" : "=f"(lo), "=f"(hi) : "l"(v));
}
__device__ __forceinline__ void ffma2(ull& d, ull a, ull b) {
    asm("fma.rn.f32x2 %0, %1, %2, %3;" : "=l"(d) : "l"(a), "l"(b), "l"(d));
}

// ---------------- Kernel 1: coeff[b,k] = mean_t tf[b,t,k], packed over b-pairs ----------------
__global__ void coeff_kernel(const float* __restrict__ tf) {
    int t = threadIdx.x;          // 512 threads
    int k = t >> 3;
    int p = t & 7;
    float s0 = 0.f, s1 = 0.f;
#pragma unroll
    for (int tt = 0; tt < NT; tt++) {
        s0 += tf[((2 * p) * NT + tt) * NK + k];
        s1 += tf[((2 * p + 1) * NT + tt) * NK + k];
    }
    g_coeff2[k * 8 + p] = pack2(s0 * 0.125f, s1 * 0.125f);
}

// ---------------- Kernel 2: lp_t[b][c][ij][oc] = sum_k coeff[b,k] * W[k,oc,c,ij] ----------------
// idx enumerates W's native inner order (oc, c, ij): coalesced reads of W; scattered writes to lp_t.
__global__ void lp_kernel(const float* __restrict__ W) {
    __shared__ ull sc[NK * 8];
    int tid = threadIdx.x;        // 256
    if (tid < NK * 8 / 2) {       // 256 threads load 512 entries (2 each)
        sc[tid] = g_coeff2[tid];
        sc[tid + 256] = g_coeff2[tid + 256];
    }
    __syncthreads();

    int idx = blockIdx.x * 256 + tid;   // < 409600 (grid 1600)
    int o   = idx / 3200;
    int rem = idx - o * 3200;
    int c   = rem / 25;
    int ij  = rem - c * 25;

    ull acc[8];
#pragma unroll
    for (int p = 0; p < 8; p++) acc[p] = 0ULL;

#pragma unroll 4
    for (int k = 0; k < NK; k++) {
        ull w2 = bcast2(W[k * 409600 + idx]);
#pragma unroll
        for (int p = 0; p < 8; p++) ffma2(acc[p], w2, sc[k * 8 + p]);
    }

    int outbase = (c * 25 + ij) * 128 + o;
#pragma unroll
    for (int p = 0; p < 8; p++) {
        float f0, f1; unpack2(acc[p], f0, f1);
        g_lp[(2 * p) * 409600 + outbase]     = f0;
        g_lp[(2 * p + 1) * 409600 + outbase] = f1;
    }
}

// ---------------- Kernel 3: direct conv, f32x2-packed over oc pairs ----------------
// Block: (b, ocb of 32 channels, 16x16 spatial tile). 256 threads.
// Thread: 2x2 spatial x 8 oc = 16 f32x2 accumulators.
__global__ void __launch_bounds__(256, 2)
conv_kernel(const float* __restrict__ x, float* __restrict__ out) {
    __shared__ __align__(16) float sx[2 * 400];   // 2 cins x 20x20 halo tile
    __shared__ __align__(16) float sw[2 * 800];   // 2 cins x 25 ij x 32 oc

    int tid = threadIdx.x;
    int b   = blockIdx.z;
    int ocb = blockIdx.y;
    int th  = blockIdx.x >> 2;
    int tw  = blockIdx.x & 3;
    int h0  = th * 16, w0 = tw * 16;

    int og  = tid >> 6;        // 0..3 : oc group of 8
    int s   = tid & 63;
    int sxi = s & 7;           // 0..7
    int syi = s >> 3;          // 0..7

    const float* xb  = x + b * CIN * (HH * WW);
    const float* lpb = g_lp + b * 409600 + ocb * 32;

    ull acc[16];
#pragma unroll
    for (int q = 0; q < 16; q++) acc[q] = 0ULL;

    for (int c0 = 0; c0 < CIN; c0 += 2) {
        // ---- stage input halo tiles (2 cins x 20x20) ----
        for (int l = tid; l < 800; l += 256) {
            int cc = (l >= 400) ? 1 : 0;
            int r  = l - cc * 400;
            int row = r / 20;
            int col = r - row * 20;
            int gh = h0 + row - 2, gw = w0 + col - 2;
            float v = 0.f;
            if (gh >= 0 && gh < HH && gw >= 0 && gw < WW)
                v = xb[(c0 + cc) * (HH * WW) + gh * WW + gw];
            sx[l] = v;
        }
        // ---- stage weights (2 cins x 25 x 32 oc), oc-contiguous ----
        for (int l = tid; l < 1600; l += 256) {
            int cc = (l >= 800) ? 1 : 0;
            int rr = l - cc * 800;
            int ij = rr >> 5;
            int oc = rr & 31;
            sw[l] = lpb[((c0 + cc) * 25 + ij) * 128 + oc];
        }
        __syncthreads();

#pragma unroll
        for (int cc = 0; cc < 2; cc++) {
            const float* sxp = sx + cc * 400 + (2 * syi) * 20 + 2 * sxi;
            const ull*   swb = (const ull*)(sw + cc * 800) + og * 4;
#pragma unroll
            for (int i = 0; i < 5; i++) {
                float r0[6], r1[6];
                const float2* p0 = (const float2*)(sxp + i * 20);
                const float2* p1 = (const float2*)(sxp + (i + 1) * 20);
#pragma unroll
                for (int m = 0; m < 3; m++) {
                    float2 v0 = p0[m]; r0[2 * m] = v0.x; r0[2 * m + 1] = v0.y;
                    float2 v1 = p1[m]; r1[2 * m] = v1.x; r1[2 * m + 1] = v1.y;
                }
#pragma unroll
                for (int j = 0; j < 5; j++) {
                    ull x00 = bcast2(r0[j]);
                    ull x01 = bcast2(r0[j + 1]);
                    ull x10 = bcast2(r1[j]);
                    ull x11 = bcast2(r1[j + 1]);
                    const ull* wp = swb + (i * 5 + j) * 16;
                    ull wa = wp[0], wb2 = wp[1], wc = wp[2], wd = wp[3];
                    ffma2(acc[0],  x00, wa); ffma2(acc[1],  x00, wb2);
                    ffma2(acc[2],  x00, wc); ffma2(acc[3],  x00, wd);
                    ffma2(acc[4],  x01, wa); ffma2(acc[5],  x01, wb2);
                    ffma2(acc[6],  x01, wc); ffma2(acc[7],  x01, wd);
                    ffma2(acc[8],  x10, wa); ffma2(acc[9],  x10, wb2);
                    ffma2(acc[10], x10, wc); ffma2(acc[11], x10, wd);
                    ffma2(acc[12], x11, wa); ffma2(acc[13], x11, wb2);
                    ffma2(acc[14], x11, wc); ffma2(acc[15], x11, wd);
                }
            }
        }
        __syncthreads();
    }

    // ---- epilogue: unpack and store ----
    int ocbase = ocb * 32 + og * 8;
#pragma unroll
    for (int sI = 0; sI < 4; sI++) {
        int dy = sI >> 1, dx = sI & 1;
        int hh = h0 + 2 * syi + dy;
        int ww = w0 + 2 * sxi + dx;
        float* op = out + ((b * COUT + ocbase) * HH + hh) * WW + ww;
#pragma unroll
        for (int p = 0; p < 4; p++) {
            float f0, f1; unpack2(acc[sI * 4 + p], f0, f1);
            op[(2 * p) * (HH * WW)]     = f0;
            op[(2 * p + 1) * (HH * WW)] = f1;
        }
    }
}

extern "C" void kernel_launch(void* const* d_in, const int* in_sizes, int n_in,
                              void* d_out, int out_size) {
    const float* x  = nullptr;
    const float* tf = nullptr;
    const float* W  = nullptr;
    for (int i = 0; i < n_in; i++) {
        if (in_sizes[i] == NB * CIN * HH * WW)            x  = (const float*)d_in[i];
        else if (in_sizes[i] == NB * NT * NK)             tf = (const float*)d_in[i];
        else if (in_sizes[i] == NK * COUT * CIN * 25)     W  = (const float*)d_in[i];
    }
    float* out = (float*)d_out;

    coeff_kernel<<<1, 512>>>(tf);
    lp_kernel<<<1600, 256>>>(W);
    conv_kernel<<<dim3(16, 4, NB), 256>>>(x, out);
}

// round 6
// speedup vs baseline: 3.1787x; 3.1787x over previous
#include <cuda_runtime.h>
#include <cstdint>

typedef unsigned long long ull;

// Problem constants
#define NB   16
#define NT   8
#define NK   64
#define CIN  128
#define COUT 128
#define HH   64
#define WW   64

// g_lp: tf32-bit weights in m16n8k8 A-fragment order:
// [b][ij 25][kc 16][mt 8][lane 32][q 4]   (b stride 409600, ij stride 16384, kc stride 1024)
// element (oc, cin): kc=cin>>3, cl=cin&7, kb=cl&3, qk=cl>>2;
//                    rl=oc&15, mt=oc>>4, rg=rl&7, qr=rl>>3;
//                    lane=rg*4+kb, q=qk*2+qr
__device__ uint32_t g_lp[NB * 409600];
__device__ ull g_coeff2[NK * 8];

// ---------------- helpers ----------------
__device__ __forceinline__ ull bcast2(float x) {
    ull r; asm("mov.b64 %0, {%1, %1};" : "=l"(r) : "f"(x)); return r;
}
__device__ __forceinline__ ull pack2(float lo, float hi) {
    ull r; asm("mov.b64 %0, {%1, %2};" : "=l"(r) : "f"(lo), "f"(hi)); return r;
}
__device__ __forceinline__ void unpack2(ull v, float& lo, float& hi) {
    asm("mov.b64 {%0, %1}, %2;" : "=f"(lo), "=f"(hi) : "l"(v));
}
__device__ __forceinline__ void ffma2(ull& d, ull a, ull b) {
    asm("fma.rn.f32x2 %0, %1, %2, %3;" : "=l"(d) : "l"(a), "l"(b), "l"(d));
}
__device__ __forceinline__ uint32_t f2tf32(float f) {
    uint32_t v; asm("cvt.rna.tf32.f32 %0, %1;" : "=r"(v) : "f"(f)); return v;
}
// m16n8k8 tf32 MMA: D(16x8,f32) += A(16x8 tf32, row) * B(8x8 tf32, col)
__device__ __forceinline__ void mma_tf32(float* d, const uint4& a, uint32_t b0, uint32_t b1) {
    asm volatile(
        "mma.sync.aligned.m16n8k8.row.col.f32.tf32.tf32.f32 "
        "{%0,%1,%2,%3}, {%4,%5,%6,%7}, {%8,%9}, {%0,%1,%2,%3};\n"
        : "+f"(d[0]), "+f"(d[1]), "+f"(d[2]), "+f"(d[3])
        : "r"(a.x), "r"(a.y), "r"(a.z), "r"(a.w), "r"(b0), "r"(b1));
}

// ---------------- Kernel 1: coeff[b,k] = mean_t tf[b,t,k] ----------------
__global__ void coeff_kernel(const float* __restrict__ tf) {
    int t = threadIdx.x;          // 512 threads
    int k = t >> 3;
    int p = t & 7;
    float s0 = 0.f, s1 = 0.f;
#pragma unroll
    for (int tt = 0; tt < NT; tt++) {
        s0 += tf[((2 * p) * NT + tt) * NK + k];
        s1 += tf[((2 * p + 1) * NT + tt) * NK + k];
    }
    g_coeff2[k * 8 + p] = pack2(s0 * 0.125f, s1 * 0.125f);
}

// ---------------- Kernel 2: fragment-ordered, tf32-converted layer params ----------------
__global__ void lp_kernel(const float* __restrict__ W) {
    __shared__ ull sc[NK * 8];
    int tid = threadIdx.x;        // 256
    sc[tid] = g_coeff2[tid];
    sc[tid + 256] = g_coeff2[tid + 256];
    __syncthreads();

    int idx = blockIdx.x * 256 + tid;   // < 409600 (grid 1600)
    int o   = idx / 3200;
    int rem = idx - o * 3200;
    int c   = rem / 25;
    int ij  = rem - c * 25;

    ull acc[8];
#pragma unroll
    for (int p = 0; p < 8; p++) acc[p] = 0ULL;

#pragma unroll 4
    for (int k = 0; k < NK; k++) {
        ull w2 = bcast2(W[k * 409600 + idx]);
#pragma unroll
        for (int p = 0; p < 8; p++) ffma2(acc[p], w2, sc[k * 8 + p]);
    }

    // fragment-order output index
    int kc = c >> 3, cl = c & 7;
    int kb = cl & 3, qk = cl >> 2;
    int rl = o & 15, mt = o >> 4;
    int rg = rl & 7, qr = rl >> 3;
    int outoff = ij * 16384 + kc * 1024 + mt * 128 + (rg * 4 + kb) * 4 + (qk * 2 + qr);

#pragma unroll
    for (int p = 0; p < 8; p++) {
        float f0, f1; unpack2(acc[p], f0, f1);
        g_lp[(2 * p) * 409600 + outoff]     = f2tf32(f0);
        g_lp[(2 * p + 1) * 409600 + outoff] = f2tf32(f1);
    }
}

// ---------------- Kernel 3: implicit-GEMM conv via mma.sync tf32 ----------------
// CTA: b x 8-row supertile (2 sequential 4-row tiles). 512 threads, 16 warps.
// Warp (mrow = wid&3, ro = wid>>2): 32 oc x 64 w of output row r0+ro.
// x tile in smem: 8 cins x 8 rows x 72 w (stride 584 words -> conflict-free B frags).
#define XSTRIDE 584

__global__ void __launch_bounds__(512, 1)
conv_kernel(const float* __restrict__ x, float* __restrict__ out) {
    __shared__ uint32_t sx[8 * XSTRIDE];   // 18688 B

    int tid  = threadIdx.x;
    int lane = tid & 31, wid = tid >> 5;
    int mrow = wid & 3, ro = wid >> 2;     // mrow: oc quarter, ro: row in tile
    int b    = blockIdx.y;

    const float*    xb  = x + b * CIN * (HH * WW);
    const uint32_t* lpb = g_lp + b * 409600;
    const uint32_t* abase = lpb + mrow * 256 + lane * 4;   // mt = 2*mrow

    int g  = lane >> 2;    // group id (rows / n col)
    int m4 = lane & 3;

    for (int tile = 0; tile < 2; tile++) {
        int r0 = blockIdx.x * 8 + tile * 4;

        float d[2][8][4];
#pragma unroll
        for (int mt = 0; mt < 2; mt++)
#pragma unroll
            for (int nt = 0; nt < 8; nt++)
#pragma unroll
                for (int q = 0; q < 4; q++) d[mt][nt][q] = 0.f;

        // prefetch A fragments for it = 0 (ij=0, kc=0)
        // mt stride in g_lp is 128 words = 32 uint4s  (p[32], NOT p[8])
        uint4 An0, An1;
        {
            const uint4* p = (const uint4*)abase;
            An0 = p[0]; An1 = p[32];
        }

        for (int it = 0; it < 400; it++) {
            int c0i = it / 25, ij = it - c0i * 25;

            if (ij == 0) {
                __syncthreads();
                int c0 = c0i * 8;
                for (int q = tid; q < 8 * 576; q += 512) {
                    int cl = q / 576, r = q - cl * 576;
                    int ur = r / 72, uc = r - ur * 72;
                    int gh = r0 + ur - 2, gw = uc - 2;
                    float v = 0.f;
                    if (gh >= 0 && gh < HH && gw >= 0 && gw < WW)
                        v = xb[((c0 + cl) << 12) + (gh << 6) + gw];
                    sx[cl * XSTRIDE + ur * 72 + uc] = f2tf32(v);
                }
                __syncthreads();
            }

            uint4 A0 = An0, A1 = An1;
            if (it + 1 < 400) {
                int itn = it + 1;
                int c0n = itn / 25, ijn = itn - c0n * 25;
                const uint4* p = (const uint4*)(abase + ijn * 16384 + c0n * 1024);
                An0 = p[0]; An1 = p[32];
            }

            int i = ij / 5, j = ij - i * 5;
            int boff = m4 * XSTRIDE + (ro + i) * 72 + j + g;
#pragma unroll
            for (int nt = 0; nt < 8; nt++) {
                uint32_t b0 = sx[boff + nt * 8];
                uint32_t b1 = sx[boff + nt * 8 + 4 * XSTRIDE];
                mma_tf32(d[0][nt], A0, b0, b1);
                mma_tf32(d[1][nt], A1, b0, b1);
            }
        }

        // epilogue: D(row=g/g+8, col=2*m4/2*m4+1) per (mt, nt)
        int h = r0 + ro;
#pragma unroll
        for (int mt = 0; mt < 2; mt++) {
#pragma unroll
            for (int qr = 0; qr < 2; qr++) {
                int oc = mrow * 32 + mt * 16 + g + qr * 8;
                float* op = out + ((b * COUT + oc) * HH + h) * WW;
#pragma unroll
                for (int nt = 0; nt < 8; nt++) {
                    float2 v;
                    v.x = d[mt][nt][qr * 2];
                    v.y = d[mt][nt][qr * 2 + 1];
                    *(float2*)(op + nt * 8 + 2 * m4) = v;
                }
            }
        }
    }
}

extern "C" void kernel_launch(void* const* d_in, const int* in_sizes, int n_in,
                              void* d_out, int out_size) {
    const float* x  = nullptr;
    const float* tf = nullptr;
    const float* W  = nullptr;
    for (int i = 0; i < n_in; i++) {
        if (in_sizes[i] == NB * CIN * HH * WW)        x  = (const float*)d_in[i];
        else if (in_sizes[i] == NB * NT * NK)         tf = (const float*)d_in[i];
        else if (in_sizes[i] == NK * COUT * CIN * 25) W  = (const float*)d_in[i];
    }
    float* out = (float*)d_out;

    coeff_kernel<<<1, 512>>>(tf);
    lp_kernel<<<1600, 256>>>(W);
    conv_kernel<<<dim3(8, NB), 512>>>(x, out);
}

// round 7
// speedup vs baseline: 6.4404x; 2.0261x over previous
#include <cuda_runtime.h>
#include <cstdint>

typedef unsigned long long ull;

// Problem constants
#define NB   16
#define NT   8
#define NK   64
#define CIN  128
#define COUT 128
#define HH   64
#define WW   64

// g_lp: fp16x2 weights in m16n8k16 A-fragment order:
// [b][ij 25][kc 8][mt 8][lane 32][q 4]   (b stride 204800, ij stride 8192, kc stride 1024)
// element (oc, cin): kc=cin>>4, cp=(cin>>1)&7, lo=cin&1 (lo->low half of fp16x2);
//                    kb=cp&3, qk=cp>>2; rl=oc&15, mt=oc>>4, rg=rl&7, qr=rl>>3;
//                    lane=rg*4+kb, q=qk*2+qr
__device__ uint32_t g_lp[NB * 204800];
__device__ ull g_coeff2[NK * 8];

// ---------------- helpers ----------------
__device__ __forceinline__ ull bcast2(float x) {
    ull r; asm("mov.b64 %0, {%1, %1};" : "=l"(r) : "f"(x)); return r;
}
__device__ __forceinline__ ull pack2(float lo, float hi) {
    ull r; asm("mov.b64 %0, {%1, %2};" : "=l"(r) : "f"(lo), "f"(hi)); return r;
}
__device__ __forceinline__ void unpack2(ull v, float& lo, float& hi) {
    asm("mov.b64 {%0, %1}, %2;" : "=f"(lo), "=f"(hi) : "l"(v));
}
__device__ __forceinline__ void ffma2(ull& d, ull a, ull b) {
    asm("fma.rn.f32x2 %0, %1, %2, %3;" : "=l"(d) : "l"(a), "l"(b), "l"(d));
}
// pack two f32 into fp16x2: lo -> low 16 bits, hi -> high 16 bits
__device__ __forceinline__ uint32_t pack_h2(float lo, float hi) {
    uint32_t v; asm("cvt.rn.f16x2.f32 %0, %1, %2;" : "=r"(v) : "f"(hi), "f"(lo)); return v;
}
// m16n8k16 fp16 MMA: D(16x8,f32) += A(16x16 f16, row) * B(16x8 f16, col)
__device__ __forceinline__ void mma_f16(float* d, const uint4& a, uint32_t b0, uint32_t b1) {
    asm volatile(
        "mma.sync.aligned.m16n8k16.row.col.f32.f16.f16.f32 "
        "{%0,%1,%2,%3}, {%4,%5,%6,%7}, {%8,%9}, {%0,%1,%2,%3};\n"
        : "+f"(d[0]), "+f"(d[1]), "+f"(d[2]), "+f"(d[3])
        : "r"(a.x), "r"(a.y), "r"(a.z), "r"(a.w), "r"(b0), "r"(b1));
}

// ---------------- Kernel 1: coeff[b,k] = mean_t tf[b,t,k] ----------------
__global__ void coeff_kernel(const float* __restrict__ tf) {
    int t = threadIdx.x;          // 512 threads
    int k = t >> 3;
    int p = t & 7;
    float s0 = 0.f, s1 = 0.f;
#pragma unroll
    for (int tt = 0; tt < NT; tt++) {
        s0 += tf[((2 * p) * NT + tt) * NK + k];
        s1 += tf[((2 * p + 1) * NT + tt) * NK + k];
    }
    g_coeff2[k * 8 + p] = pack2(s0 * 0.125f, s1 * 0.125f);
}

// ---------------- Kernel 2: fragment-ordered fp16x2 layer params ----------------
// One thread per (o, cin-pair cp, ij): computes both cins of the pair for all 16 b.
__global__ void lp_kernel(const float* __restrict__ W) {
    __shared__ ull sc[NK * 8];
    int tid = threadIdx.x;        // 256
    sc[tid] = g_coeff2[tid];
    sc[tid + 256] = g_coeff2[tid + 256];
    __syncthreads();

    int idx = blockIdx.x * 256 + tid;   // < 204800 (grid 800)
    int o   = idx / 1600;
    int rem = idx - o * 1600;
    int cp  = rem / 25;
    int ij  = rem - cp * 25;

    const float* W0 = W + o * 3200 + (2 * cp) * 25 + ij;        // even cin
    const float* W1 = W0 + 25;                                  // odd cin

    ull a0[8], a1[8];
#pragma unroll
    for (int p = 0; p < 8; p++) { a0[p] = 0ULL; a1[p] = 0ULL; }

#pragma unroll 4
    for (int k = 0; k < NK; k++) {
        ull w0 = bcast2(W0[k * 409600]);
        ull w1 = bcast2(W1[k * 409600]);
#pragma unroll
        for (int p = 0; p < 8; p++) {
            ffma2(a0[p], w0, sc[k * 8 + p]);
            ffma2(a1[p], w1, sc[k * 8 + p]);
        }
    }

    // fragment-order output index
    int kc = cp >> 3, cpl = cp & 7;
    int kb = cpl & 3, qk = cpl >> 2;
    int rl = o & 15, mt = o >> 4;
    int rg = rl & 7, qr = rl >> 3;
    int outoff = ij * 8192 + kc * 1024 + mt * 128 + (rg * 4 + kb) * 4 + (qk * 2 + qr);

#pragma unroll
    for (int p = 0; p < 8; p++) {
        float e0, e1, d0, d1;
        unpack2(a0[p], e0, e1);   // even cin, b = 2p / 2p+1
        unpack2(a1[p], d0, d1);   // odd  cin
        g_lp[(2 * p) * 204800 + outoff]     = pack_h2(e0, d0);
        g_lp[(2 * p + 1) * 204800 + outoff] = pack_h2(e1, d1);
    }
}

// ---------------- Kernel 3: implicit-GEMM conv via mma.sync fp16 k16 ----------------
// CTA: b x 8-row supertile (2 sequential 4-row tiles). 512 threads, 16 warps.
// Warp (mrow = wid&3, ro = wid>>2): 32 oc x 64 w of output row r0+ro.
// x tile in smem: 8 cin-pairs x 8 rows x 72 w fp16x2 (stride 584 -> conflict-free B frags).
#define XSTRIDE 584

__global__ void __launch_bounds__(512, 1)
conv_kernel(const float* __restrict__ x, float* __restrict__ out) {
    __shared__ uint32_t sx[8 * XSTRIDE];   // 18688 B

    int tid  = threadIdx.x;
    int lane = tid & 31, wid = tid >> 5;
    int mrow = wid & 3, ro = wid >> 2;
    int b    = blockIdx.y;

    const float*    xb  = x + b * CIN * (HH * WW);
    const uint32_t* lpb = g_lp + b * 204800;
    const uint32_t* abase = lpb + mrow * 256 + lane * 4;   // mt = 2*mrow

    int g  = lane >> 2;
    int m4 = lane & 3;

    for (int tile = 0; tile < 2; tile++) {
        int r0 = blockIdx.x * 8 + tile * 4;

        float d[2][8][4];
#pragma unroll
        for (int mt = 0; mt < 2; mt++)
#pragma unroll
            for (int nt = 0; nt < 8; nt++)
#pragma unroll
                for (int q = 0; q < 4; q++) d[mt][nt][q] = 0.f;

        // prefetch A fragments for it = 0 (ij=0, kc=0); mt stride = 128 words = 32 uint4
        uint4 An0, An1;
        {
            const uint4* p = (const uint4*)abase;
            An0 = p[0]; An1 = p[32];
        }

        for (int it = 0; it < 200; it++) {
            int c0i = it / 25, ij = it - c0i * 25;

            if (ij == 0) {
                __syncthreads();
                int c0 = c0i * 16;
                for (int q = tid; q < 8 * 576; q += 512) {
                    int pr = q / 576, r = q - pr * 576;
                    int ur = r / 72, uc = r - ur * 72;
                    int gh = r0 + ur - 2, gw = uc - 2;
                    float v0 = 0.f, v1 = 0.f;
                    if (gh >= 0 && gh < HH && gw >= 0 && gw < WW) {
                        const float* px = xb + ((c0 + 2 * pr) << 12) + (gh << 6) + gw;
                        v0 = px[0];
                        v1 = px[1 << 12];
                    }
                    sx[pr * XSTRIDE + ur * 72 + uc] = pack_h2(v0, v1);
                }
                __syncthreads();
            }

            uint4 A0 = An0, A1 = An1;
            if (it + 1 < 200) {
                int itn = it + 1;
                int c0n = itn / 25, ijn = itn - c0n * 25;
                const uint4* p = (const uint4*)(abase + ijn * 8192 + c0n * 1024);
                An0 = p[0]; An1 = p[32];
            }

            int i = ij / 5, j = ij - i * 5;
            int boff = m4 * XSTRIDE + (ro + i) * 72 + j + g;
#pragma unroll
            for (int nt = 0; nt < 8; nt++) {
                uint32_t b0 = sx[boff + nt * 8];
                uint32_t b1 = sx[boff + nt * 8 + 4 * XSTRIDE];
                mma_f16(d[0][nt], A0, b0, b1);
                mma_f16(d[1][nt], A1, b0, b1);
            }
        }

        // epilogue: D(row=g/g+8, col=2*m4/2*m4+1) per (mt, nt)
        int h = r0 + ro;
#pragma unroll
        for (int mt = 0; mt < 2; mt++) {
#pragma unroll
            for (int qr = 0; qr < 2; qr++) {
                int oc = mrow * 32 + mt * 16 + g + qr * 8;
                float* op = out + ((b * COUT + oc) * HH + h) * WW;
#pragma unroll
                for (int nt = 0; nt < 8; nt++) {
                    float2 v;
                    v.x = d[mt][nt][qr * 2];
                    v.y = d[mt][nt][qr * 2 + 1];
                    *(float2*)(op + nt * 8 + 2 * m4) = v;
                }
            }
        }
    }
}

extern "C" void kernel_launch(void* const* d_in, const int* in_sizes, int n_in,
                              void* d_out, int out_size) {
    const float* x  = nullptr;
    const float* tf = nullptr;
    const float* W  = nullptr;
    for (int i = 0; i < n_in; i++) {
        if (in_sizes[i] == NB * CIN * HH * WW)        x  = (const float*)d_in[i];
        else if (in_sizes[i] == NB * NT * NK)         tf = (const float*)d_in[i];
        else if (in_sizes[i] == NK * COUT * CIN * 25) W  = (const float*)d_in[i];
    }
    float* out = (float*)d_out;

    coeff_kernel<<<1, 512>>>(tf);
    lp_kernel<<<800, 256>>>(W);
    conv_kernel<<<dim3(8, NB), 512>>>(x, out);
}